// round 1
// baseline (speedup 1.0000x reference)
#include <cuda_runtime.h>
#include <cuda_bf16.h>
#include <stdint.h>

// PeriodicDistance:
//   cell_shifts[e,m] = sum_n shifts[e,n] * box[batch[e], n, m]
//   dr = pos[j] - pos[i] + cell_shifts ; weight = |dr| ; vec = -dr
// Output (float32, flattened tuple in return order):
//   [0,E)      : edge_index[0,:]  (cast)
//   [E,2E)     : edge_index[1,:]  (cast)
//   [2E,3E)    : edge_weight
//   [3E,6E)    : edge_vec, row-major [E,3]
//   [6E,9E)    : shifts_idx, row-major [E,3] (cast)

__global__ void __launch_bounds__(256)
pd_kernel_full(const float* __restrict__ pos,
               const float* __restrict__ box,
               const int*   __restrict__ ei,
               const int*   __restrict__ shifts,
               const int*   __restrict__ batch,
               float*       __restrict__ out,
               int E, int n_boxes)
{
    int e = blockIdx.x * blockDim.x + threadIdx.x;
    if (e >= E) return;

    // --- index loads (coalesced streams) ---
    int i = __ldg(ei + e);
    int j = __ldg(ei + (size_t)E + e);

    const int* sp = shifts + 3u * (size_t)e;
    int sx = __ldg(sp + 0);
    int sy = __ldg(sp + 1);
    int sz = __ldg(sp + 2);

    // --- box row selection (uniform broadcast when n_boxes==1) ---
    const float* b = box;
    if (n_boxes > 1) b = box + 9u * (size_t)__ldg(batch + e);
    float fx = (float)sx, fy = (float)sy, fz = (float)sz;
    // cs[m] = fx*b[0,m] + fy*b[1,m] + fz*b[2,m]
    float csx = fx * __ldg(b + 0) + fy * __ldg(b + 3) + fz * __ldg(b + 6);
    float csy = fx * __ldg(b + 1) + fy * __ldg(b + 4) + fz * __ldg(b + 7);
    float csz = fx * __ldg(b + 2) + fy * __ldg(b + 5) + fz * __ldg(b + 8);

    // --- position gathers (L2-resident: pos is 2.4 MB) ---
    const float* pi = pos + 3u * (size_t)i;
    const float* pj = pos + 3u * (size_t)j;
    float drx = __ldg(pj + 0) - __ldg(pi + 0) + csx;
    float dry = __ldg(pj + 1) - __ldg(pi + 1) + csy;
    float drz = __ldg(pj + 2) - __ldg(pi + 2) + csz;

    float w = sqrtf(drx * drx + dry * dry + drz * drz);

    // --- stores (all streams warp-contiguous) ---
    size_t Es = (size_t)E;
    out[e]          = (float)i;
    out[Es + e]     = (float)j;
    out[2 * Es + e] = w;

    float* v = out + 3 * Es + 3u * (size_t)e;
    v[0] = -drx; v[1] = -dry; v[2] = -drz;

    float* sh = out + 6 * Es + 3u * (size_t)e;
    sh[0] = fx; sh[1] = fy; sh[2] = fz;
}

// Fallback layout: [weight(E) | vec(E,3)] only, if out_size == 4E.
__global__ void __launch_bounds__(256)
pd_kernel_wv(const float* __restrict__ pos,
             const float* __restrict__ box,
             const int*   __restrict__ ei,
             const int*   __restrict__ shifts,
             const int*   __restrict__ batch,
             float*       __restrict__ out,
             int E, int n_boxes)
{
    int e = blockIdx.x * blockDim.x + threadIdx.x;
    if (e >= E) return;

    int i = __ldg(ei + e);
    int j = __ldg(ei + (size_t)E + e);
    const int* sp = shifts + 3u * (size_t)e;
    float fx = (float)__ldg(sp + 0);
    float fy = (float)__ldg(sp + 1);
    float fz = (float)__ldg(sp + 2);

    const float* b = box;
    if (n_boxes > 1) b = box + 9u * (size_t)__ldg(batch + e);
    float csx = fx * __ldg(b + 0) + fy * __ldg(b + 3) + fz * __ldg(b + 6);
    float csy = fx * __ldg(b + 1) + fy * __ldg(b + 4) + fz * __ldg(b + 7);
    float csz = fx * __ldg(b + 2) + fy * __ldg(b + 5) + fz * __ldg(b + 8);

    const float* pi = pos + 3u * (size_t)i;
    const float* pj = pos + 3u * (size_t)j;
    float drx = __ldg(pj + 0) - __ldg(pi + 0) + csx;
    float dry = __ldg(pj + 1) - __ldg(pi + 1) + csy;
    float drz = __ldg(pj + 2) - __ldg(pi + 2) + csz;

    out[e] = sqrtf(drx * drx + dry * dry + drz * drz);
    float* v = out + (size_t)E + 3u * (size_t)e;
    v[0] = -drx; v[1] = -dry; v[2] = -drz;
}

extern "C" void kernel_launch(void* const* d_in, const int* in_sizes, int n_in,
                              void* d_out, int out_size)
{
    // metadata order: pos, box, edge_index, shifts_idx, batch_map
    const float* pos    = (const float*)d_in[0];
    const float* box    = (const float*)d_in[1];
    const int*   ei     = (const int*)  d_in[2];
    const int*   shifts = (const int*)  d_in[3];
    const int*   batch  = (const int*)  d_in[4];

    int E       = in_sizes[4];        // batch_map length == number of edges
    int n_boxes = in_sizes[1] / 9;    // box is [B,3,3]
    float* out  = (float*)d_out;

    int threads = 256;
    int blocks  = (E + threads - 1) / threads;

    if ((long long)out_size == 4LL * E) {
        pd_kernel_wv<<<blocks, threads>>>(pos, box, ei, shifts, batch, out, E, n_boxes);
    } else {
        pd_kernel_full<<<blocks, threads>>>(pos, box, ei, shifts, batch, out, E, n_boxes);
    }
}

// round 2
// speedup vs baseline: 1.1870x; 1.1870x over previous
#include <cuda_runtime.h>
#include <cuda_bf16.h>
#include <stdint.h>

// PeriodicDistance — vectorized (4 edges/thread, 128-bit streams) + padded
// float4 position scratch for single-sector gathers.
//
// Output layout (float32, flattened tuple in return order):
//   [0,E)      : edge_index[0,:]  (cast)
//   [E,2E)     : edge_index[1,:]  (cast)
//   [2E,3E)    : edge_weight
//   [3E,6E)    : edge_vec, row-major [E,3]
//   [6E,9E)    : shifts_idx, row-major [E,3] (cast)

#define MAX_ATOMS_PAD (1 << 19)   // 524288 atoms * 16B = 8 MB static scratch
__device__ float4 g_pos4[MAX_ATOMS_PAD];

// --- prologue: pos[N,3] -> g_pos4[N] (16B rows) ---
__global__ void __launch_bounds__(256)
pd_pad_pos(const float* __restrict__ pos, int n_atoms)
{
    int a = blockIdx.x * blockDim.x + threadIdx.x;
    if (a >= n_atoms) return;
    const float* p = pos + 3u * (size_t)a;
    g_pos4[a] = make_float4(p[0], p[1], p[2], 0.0f);
}

// --- main: 4 edges per thread, fully vectorized streams ---
__global__ void __launch_bounds__(256)
pd_kernel_vec4(const float* __restrict__ box,
               const int*   __restrict__ ei,
               const int*   __restrict__ shifts,
               const int*   __restrict__ batch,
               float*       __restrict__ out,
               int E4,          // E/4
               int n_boxes)
{
    int t = blockIdx.x * blockDim.x + threadIdx.x;
    if (t >= E4) return;

    size_t Es = 4u * (size_t)E4;   // E

    // indices: 4 src + 4 dst
    const int4* ei4 = (const int4*)ei;
    int4 ia = __ldg(ei4 + t);            // edge_index[0, 4t..4t+3]
    int4 ib = __ldg(ei4 + E4 + t);       // edge_index[1, 4t..4t+3]

    // shifts: 12 ints = 3 x int4
    const int4* sh4 = (const int4*)shifts;
    int4 s0 = __ldg(sh4 + 3u * (size_t)t + 0);
    int4 s1 = __ldg(sh4 + 3u * (size_t)t + 1);
    int4 s2 = __ldg(sh4 + 3u * (size_t)t + 2);
    // unpack per-edge (sx,sy,sz)
    float fx0 = (float)s0.x, fy0 = (float)s0.y, fz0 = (float)s0.z;
    float fx1 = (float)s0.w, fy1 = (float)s1.x, fz1 = (float)s1.y;
    float fx2 = (float)s1.z, fy2 = (float)s1.w, fz2 = (float)s2.x;
    float fx3 = (float)s2.y, fy3 = (float)s2.z, fz3 = (float)s2.w;

    // box rows (uniform broadcast for single structure)
    float b00, b01, b02, b10, b11, b12, b20, b21, b22;
    if (n_boxes == 1) {
        b00 = __ldg(box + 0); b01 = __ldg(box + 1); b02 = __ldg(box + 2);
        b10 = __ldg(box + 3); b11 = __ldg(box + 4); b12 = __ldg(box + 5);
        b20 = __ldg(box + 6); b21 = __ldg(box + 7); b22 = __ldg(box + 8);
    } else {
        // rare path: use first edge's batch for all 4 (only correct when
        // batches agree; guarded by launcher which falls back to scalar
        // kernel when n_boxes > 1)
        b00 = b01 = b02 = b10 = b11 = b12 = b20 = b21 = b22 = 0.0f;
    }

    // gathers: one LDG.128 per endpoint
    float4 pa0 = g_pos4[ia.x], pa1 = g_pos4[ia.y], pa2 = g_pos4[ia.z], pa3 = g_pos4[ia.w];
    float4 pb0 = g_pos4[ib.x], pb1 = g_pos4[ib.y], pb2 = g_pos4[ib.z], pb3 = g_pos4[ib.w];

    // dr = pb - pa + s @ box
    float drx0 = pb0.x - pa0.x + fx0 * b00 + fy0 * b10 + fz0 * b20;
    float dry0 = pb0.y - pa0.y + fx0 * b01 + fy0 * b11 + fz0 * b21;
    float drz0 = pb0.z - pa0.z + fx0 * b02 + fy0 * b12 + fz0 * b22;
    float drx1 = pb1.x - pa1.x + fx1 * b00 + fy1 * b10 + fz1 * b20;
    float dry1 = pb1.y - pa1.y + fx1 * b01 + fy1 * b11 + fz1 * b21;
    float drz1 = pb1.z - pa1.z + fx1 * b02 + fy1 * b12 + fz1 * b22;
    float drx2 = pb2.x - pa2.x + fx2 * b00 + fy2 * b10 + fz2 * b20;
    float dry2 = pb2.y - pa2.y + fx2 * b01 + fy2 * b11 + fz2 * b21;
    float drz2 = pb2.z - pa2.z + fx2 * b02 + fy2 * b12 + fz2 * b22;
    float drx3 = pb3.x - pa3.x + fx3 * b00 + fy3 * b10 + fz3 * b20;
    float dry3 = pb3.y - pa3.y + fx3 * b01 + fy3 * b11 + fz3 * b21;
    float drz3 = pb3.z - pa3.z + fx3 * b02 + fy3 * b12 + fz3 * b22;

    float4 w = make_float4(
        sqrtf(drx0 * drx0 + dry0 * dry0 + drz0 * drz0),
        sqrtf(drx1 * drx1 + dry1 * dry1 + drz1 * drz1),
        sqrtf(drx2 * drx2 + dry2 * dry2 + drz2 * drz2),
        sqrtf(drx3 * drx3 + dry3 * dry3 + drz3 * drz3));

    // stores — all float4, all 16B aligned
    float4* o0 = (float4*)(out) + t;                     // ei[0] cast
    float4* o1 = (float4*)(out + Es) + t;                // ei[1] cast
    float4* ow = (float4*)(out + 2 * Es) + t;            // weight
    float4* ov = (float4*)(out + 3 * Es) + 3u * (size_t)t;  // vec [E,3]
    float4* os = (float4*)(out + 6 * Es) + 3u * (size_t)t;  // shifts [E,3]

    *o0 = make_float4((float)ia.x, (float)ia.y, (float)ia.z, (float)ia.w);
    *o1 = make_float4((float)ib.x, (float)ib.y, (float)ib.z, (float)ib.w);
    *ow = w;
    ov[0] = make_float4(-drx0, -dry0, -drz0, -drx1);
    ov[1] = make_float4(-dry1, -drz1, -drx2, -dry2);
    ov[2] = make_float4(-drz2, -drx3, -dry3, -drz3);
    os[0] = make_float4(fx0, fy0, fz0, fx1);
    os[1] = make_float4(fy1, fz1, fx2, fy2);
    os[2] = make_float4(fz2, fx3, fy3, fz3);
}

// --- fallback scalar kernel (general layout / E not divisible by 4 / big N) ---
__global__ void __launch_bounds__(256)
pd_kernel_full(const float* __restrict__ pos,
               const float* __restrict__ box,
               const int*   __restrict__ ei,
               const int*   __restrict__ shifts,
               const int*   __restrict__ batch,
               float*       __restrict__ out,
               int E, int n_boxes)
{
    int e = blockIdx.x * blockDim.x + threadIdx.x;
    if (e >= E) return;

    int i = __ldg(ei + e);
    int j = __ldg(ei + (size_t)E + e);
    const int* sp = shifts + 3u * (size_t)e;
    float fx = (float)__ldg(sp + 0);
    float fy = (float)__ldg(sp + 1);
    float fz = (float)__ldg(sp + 2);

    const float* b = box;
    if (n_boxes > 1) b = box + 9u * (size_t)__ldg(batch + e);
    float csx = fx * __ldg(b + 0) + fy * __ldg(b + 3) + fz * __ldg(b + 6);
    float csy = fx * __ldg(b + 1) + fy * __ldg(b + 4) + fz * __ldg(b + 7);
    float csz = fx * __ldg(b + 2) + fy * __ldg(b + 5) + fz * __ldg(b + 8);

    const float* pi = pos + 3u * (size_t)i;
    const float* pj = pos + 3u * (size_t)j;
    float drx = __ldg(pj + 0) - __ldg(pi + 0) + csx;
    float dry = __ldg(pj + 1) - __ldg(pi + 1) + csy;
    float drz = __ldg(pj + 2) - __ldg(pi + 2) + csz;

    float w = sqrtf(drx * drx + dry * dry + drz * drz);

    size_t Es = (size_t)E;
    out[e]          = (float)i;
    out[Es + e]     = (float)j;
    out[2 * Es + e] = w;

    float* v = out + 3 * Es + 3u * (size_t)e;
    v[0] = -drx; v[1] = -dry; v[2] = -drz;
    float* sh = out + 6 * Es + 3u * (size_t)e;
    sh[0] = fx; sh[1] = fy; sh[2] = fz;
}

extern "C" void kernel_launch(void* const* d_in, const int* in_sizes, int n_in,
                              void* d_out, int out_size)
{
    const float* pos    = (const float*)d_in[0];
    const float* box    = (const float*)d_in[1];
    const int*   ei     = (const int*)  d_in[2];
    const int*   shifts = (const int*)  d_in[3];
    const int*   batch  = (const int*)  d_in[4];

    int E       = in_sizes[4];
    int n_atoms = in_sizes[0] / 3;
    int n_boxes = in_sizes[1] / 9;
    float* out  = (float*)d_out;

    bool fast = (E % 4 == 0) && (n_atoms <= MAX_ATOMS_PAD) && (n_boxes == 1)
                && ((long long)out_size == 9LL * E);

    if (fast) {
        int pb = (n_atoms + 255) / 256;
        pd_pad_pos<<<pb, 256>>>(pos, n_atoms);
        int E4 = E / 4;
        int blocks = (E4 + 255) / 256;
        pd_kernel_vec4<<<blocks, 256>>>(box, ei, shifts, batch, out, E4, n_boxes);
    } else {
        int blocks = (E + 255) / 256;
        pd_kernel_full<<<blocks, 256>>>(pos, box, ei, shifts, batch, out, E, n_boxes);
    }
}